// round 14
// baseline (speedup 1.0000x reference)
#include <cuda_runtime.h>
#include <cuda_fp8.h>
#include <cstdint>

#define N_ROWS 8192
#define DIM    128
#define NCLS   64
#define TI     128                 // CTA tile (M = N = 128)
#define NBI    (N_ROWS / TI)       // 64
#define NT     (NBI * 2)           // 128 partial slots per row
#define NTILES (NBI * (NBI + 1) / 2)   // 2080 upper-tri tiles
#define SROWB  144                 // padded smem row stride in BYTES (128 data + 16)
#define CPAD   33                  // scol contributor stride (pad vs 32)
#define RBLK   256                 // k_row blocks

// ---- scratch (__device__ globals; no cudaMalloc allowed) ----
__device__ uint8_t g_x8[(size_t)N_ROWS * DIM];     // normalized*sqrt(EXSCALE), e4m3
__device__ float g_negp[(size_t)N_ROWS * NT];      // [row][slot]
__device__ float g_posp[(size_t)N_ROWS * NT];
__device__ int   g_cnt[NCLS];                      // zero at load; k_row resets
__device__ float g_bsum[RBLK];
__device__ int   g_done;                           // zero at load; k_row resets

#define EXSCALE  2.8853900817779268f   // log2(e)/T, T=0.5
#define SQRT_EXS 1.6986436490789138f   // sqrt(EXSCALE)

__device__ __forceinline__ uint32_t smem_u32(const void* p) {
    uint32_t a;
    asm("{ .reg .u64 t; cvta.to.shared.u64 t, %1; cvt.u32.u64 %0, t; }" : "=r"(a) : "l"(p));
    return a;
}
__device__ __forceinline__ float ex2f(float x) {
    float r; asm("ex2.approx.f32 %0, %1;" : "=f"(r) : "f"(x)); return r;
}
__device__ __forceinline__ void ldsm4(uint32_t* r, uint32_t addr) {
    asm volatile("ldmatrix.sync.aligned.m8n8.x4.shared.b16 {%0,%1,%2,%3}, [%4];"
                 : "=r"(r[0]), "=r"(r[1]), "=r"(r[2]), "=r"(r[3]) : "r"(addr));
}
// fp8 e4m3 MMA, fp32 accumulate.
__device__ __forceinline__ void mma16832(float* d, const uint32_t* a,
                                         uint32_t b0, uint32_t b1) {
    asm volatile(
        "mma.sync.aligned.m16n8k32.row.col.f32.e4m3.e4m3.f32 "
        "{%0,%1,%2,%3}, {%4,%5,%6,%7}, {%8,%9}, {%0,%1,%2,%3};"
        : "+f"(d[0]), "+f"(d[1]), "+f"(d[2]), "+f"(d[3])
        : "r"(a[0]), "r"(a[1]), "r"(a[2]), "r"(a[3]), "r"(b0), "r"(b1));
}

// One warp per row: float4 load, shfl reduce, e4m3x4 store.
// Label histogram via integer global atomics (deterministic); g_cnt is
// guaranteed zero here (module init on first call, k_row reset afterwards).
__global__ void k_norm(const float* __restrict__ x,
                       const int* __restrict__ lab) {
    int wid  = (blockIdx.x * 256 + threadIdx.x) >> 5;   // global warp = row
    int lane = threadIdx.x & 31;
    float4 v = *(const float4*)&x[(size_t)wid * DIM + lane * 4];
    float ss = v.x * v.x + v.y * v.y + v.z * v.z + v.w * v.w;
    #pragma unroll
    for (int o = 16; o > 0; o >>= 1) ss += __shfl_xor_sync(0xffffffffu, ss, o);
    float sc = SQRT_EXS / fmaxf(sqrtf(ss), 1e-12f);
    __nv_fp8x2_storage_t lo = __nv_cvt_float2_to_fp8x2(
        make_float2(v.x * sc, v.y * sc), __NV_SATFINITE, __NV_E4M3);
    __nv_fp8x2_storage_t hi = __nv_cvt_float2_to_fp8x2(
        make_float2(v.z * sc, v.w * sc), __NV_SATFINITE, __NV_E4M3);
    uint32_t packed = (uint32_t)lo | ((uint32_t)hi << 16);
    *(uint32_t*)&g_x8[(size_t)wid * DIM + lane * 4] = packed;
    if (lane == 0) atomicAdd(&g_cnt[lab[wid] & (NCLS - 1)], 1);
}

// Upper-triangular 128x128 Gram tile (bi <= bj), fp8 tensor cores.
// 512 threads, 16 warps in a 4(M)x4(N) grid: 32x32 per warp -> acc is only
// 32 regs/thread (no spills). Row-side partials (slots 2*bj+half) combine
// warp_n quarter-pairs via smem; column-side (slots 2*bi+{0,1}) via scol.
__global__ void __launch_bounds__(512, 1)
k_pair(const int* __restrict__ lab) {
    extern __shared__ char sm[];
    char* As = sm;                                     // [128][SROWB] bytes
    char* Bs = sm + TI * SROWB;                        // [128][SROWB]
    int* labJ = (int*)(Bs + TI * SROWB);               // [128]
    int* labI = labJ + TI;                             // [128]
    // Reuse region (post-MMA): scol [2][128][CPAD] floats, then srow [2][4][128]
    float* scol = (float*)sm;                          // 33792 B
    float* srow = (float*)(sm + 2 * 128 * CPAD * 4);   // 4096 B

    int tid  = threadIdx.x;
    int w    = tid >> 5;
    int lane = tid & 31;
    int warp_m = w >> 2;                    // 0..3 -> 32-row slab
    int warp_n = w & 3;                     // 0..3 -> 32-col quarter

    // 1D triangular mapping: t = bj*(bj+1)/2 + bi, bi <= bj.
    int t4 = blockIdx.x;
    int bj = (int)((sqrt(8.0 * (double)t4 + 1.0) - 1.0) * 0.5);
    int bi = t4 - bj * (bj + 1) / 2;
    int i0 = bi * TI;
    int j0 = bj * TI;

    // Cooperative tile load: 2048 16B chunks over 512 threads.
    #pragma unroll
    for (int it = 0; it < 4; it++) {
        int idx = tid + it * 512;           // 0..2047
        int sub = idx >> 10;                // 0 = A(i), 1 = B(j)
        int loc = idx & 1023;
        int row = loc >> 3, c = loc & 7;
        int grow = (sub ? j0 : i0) + row;
        uint4 v = *(const uint4*)&g_x8[(size_t)grow * DIM + c * 16];
        char* dst = sub ? Bs : As;
        *(uint4*)(dst + row * SROWB + c * 16) = v;
    }
    if (tid < TI) labJ[tid] = lab[j0 + tid];
    else if (tid < 2 * TI) labI[tid - TI] = lab[i0 + tid - TI];
    __syncthreads();

    uint32_t asb = smem_u32(As), bsb = smem_u32(Bs);
    uint32_t a_row = (uint32_t)(warp_m * 32 + (lane & 7) + ((lane >> 3) & 1) * 8);
    uint32_t aaddr = asb + a_row * SROWB + ((lane >> 4) * 16);
    uint32_t b_n = (uint32_t)(warp_n * 32 + ((lane >> 4) << 3) + (lane & 7));
    uint32_t baddr = bsb + b_n * SROWB + (((lane >> 3) & 1) * 16);

    float acc[2][4][4];
    #pragma unroll
    for (int mf = 0; mf < 2; mf++)
        #pragma unroll
        for (int nf = 0; nf < 4; nf++)
            #pragma unroll
            for (int e = 0; e < 4; e++) acc[mf][nf][e] = 0.0f;

    #pragma unroll
    for (int ks = 0; ks < 4; ks++) {       // k32 per step, 4 steps = K128
        uint32_t a[2][4], b[2][4];
        ldsm4(a[0], aaddr + ks * 32);
        ldsm4(a[1], aaddr + 16 * SROWB + ks * 32);
        ldsm4(b[0], baddr + ks * 32);
        ldsm4(b[1], baddr + 16 * SROWB + ks * 32);
        #pragma unroll
        for (int mf = 0; mf < 2; mf++)
            #pragma unroll
            for (int nf = 0; nf < 4; nf++)
                mma16832(acc[mf][nf], a[mf], b[nf >> 1][(nf & 1) * 2],
                         b[nf >> 1][(nf & 1) * 2 + 1]);
    }

    int lj[4][2];
    #pragma unroll
    for (int nf = 0; nf < 4; nf++) {
        int j = warp_n * 32 + nf * 8 + ((lane & 3) << 1);
        lj[nf][0] = labJ[j];
        lj[nf][1] = labJ[j + 1];
    }
    int li4[2][2];
    #pragma unroll
    for (int mf = 0; mf < 2; mf++)
        #pragma unroll
        for (int rh = 0; rh < 2; rh++)
            li4[mf][rh] = labI[warp_m * 32 + mf * 16 + (lane >> 2) + rh * 8];
    __syncthreads();   // labels consumed; smem reused as scol/srow

    float colneg[4][2], colpos[4][2];
    #pragma unroll
    for (int nf = 0; nf < 4; nf++)
        colneg[nf][0] = colneg[nf][1] = colpos[nf][0] = colpos[nf][1] = 0.0f;

    // acc = dot*EXSCALE (folded into quantized vectors) -> ex2 directly.
    #pragma unroll
    for (int mf = 0; mf < 2; mf++) {
        #pragma unroll
        for (int rh = 0; rh < 2; rh++) {
            int li = li4[mf][rh];
            float neg = 0.0f, pos = 0.0f;
            #pragma unroll
            for (int nf = 0; nf < 4; nf++) {
                float s0 = ex2f(acc[mf][nf][2 * rh]);
                float s1 = ex2f(acc[mf][nf][2 * rh + 1]);
                neg += s0 + s1;
                colneg[nf][0] += s0;
                colneg[nf][1] += s1;
                if (li == lj[nf][0]) { pos += s0; colpos[nf][0] += s0; }
                if (li == lj[nf][1]) { pos += s1; colpos[nf][1] += s1; }
            }
            neg += __shfl_xor_sync(0xffffffffu, neg, 1);
            neg += __shfl_xor_sync(0xffffffffu, neg, 2);
            pos += __shfl_xor_sync(0xffffffffu, pos, 1);
            pos += __shfl_xor_sync(0xffffffffu, pos, 2);
            if ((lane & 3) == 0) {
                int rloc = warp_m * 32 + mf * 16 + (lane >> 2) + rh * 8;
                srow[warp_n * 128 + rloc]       = neg;   // [quarter][row] neg
                srow[512 + warp_n * 128 + rloc] = pos;   // [quarter][row] pos
            }
        }
    }

    // Column-side smem transpose store (32 contributors per column).
    {
        int contrib = warp_m * 8 + (lane >> 2);
        #pragma unroll
        for (int nf = 0; nf < 4; nf++) {
            int col = warp_n * 32 + nf * 8 + ((lane & 3) << 1);
            scol[(col)           * CPAD + contrib] = colneg[nf][0];
            scol[(col + 1)       * CPAD + contrib] = colneg[nf][1];
            scol[(128 + col)     * CPAD + contrib] = colpos[nf][0];
            scol[(128 + col + 1) * CPAD + contrib] = colpos[nf][1];
        }
    }
    __syncthreads();

    // Final phase: threads 0..255 -> row-side, 256..511 -> column-side.
    if (tid < 256) {
        int r = tid & 127, half = tid >> 7;          // half: cols 0-63 / 64-127
        float neg = srow[half * 256 + r]       + srow[half * 256 + 128 + r];
        float pos = srow[512 + half * 256 + r] + srow[512 + half * 256 + 128 + r];
        int grow = i0 + r;
        g_negp[(size_t)grow * NT + 2 * bj + half] = neg;
        g_posp[(size_t)grow * NT + 2 * bj + half] = pos;
    } else if (bi != bj) {
        int col = tid & 127, arr = (tid >> 7) & 1;   // 0 = neg, 1 = pos
        const float* s = scol + (arr * 128 + col) * CPAD;
        float v01 = 0.f, v23 = 0.f;
        #pragma unroll
        for (int i = 0; i < 16; i++) { v01 += s[i]; v23 += s[16 + i]; }
        float* g = arr ? g_posp : g_negp;
        g[(size_t)(j0 + col) * NT + 2 * bi]     = v01;
        g[(size_t)(j0 + col) * NT + 2 * bi + 1] = v23;
    }
}

// Per-row loss + fused final reduction. 8 threads/row, 4xfloat4 per array.
// Last block sums partials, writes out, and resets g_cnt/g_done for replay.
__global__ void k_row(const int* __restrict__ lab, float* __restrict__ out) {
    int g = blockIdx.x * 256 + threadIdx.x;
    int row = g >> 3, sub = g & 7;
    const float4* np = (const float4*)&g_negp[(size_t)row * NT + sub * 16];
    const float4* pp = (const float4*)&g_posp[(size_t)row * NT + sub * 16];
    float neg = 0.f, pos = 0.f;
    #pragma unroll
    for (int q = 0; q < 4; q++) {
        float4 a = np[q], b = pp[q];
        neg += (a.x + a.y) + (a.z + a.w);
        pos += (b.x + b.y) + (b.z + b.w);
    }
    #pragma unroll
    for (int o = 1; o < 8; o <<= 1) {
        neg += __shfl_xor_sync(0xffffffffu, neg, o);
        pos += __shfl_xor_sync(0xffffffffu, pos, o);
    }
    __shared__ float sl[32];
    __shared__ int slast;
    if (sub == 0) {
        float self = ex2f(EXSCALE);   // exp(1/T): diagonal term
        int cnt = g_cnt[lab[row] & (NCLS - 1)] - 1;
        sl[threadIdx.x >> 3] = logf(neg - self) - logf((pos - self) / (float)cnt);
    }
    __syncthreads();
    if (threadIdx.x < 32) {
        float l = sl[threadIdx.x];
        #pragma unroll
        for (int o = 16; o > 0; o >>= 1) l += __shfl_xor_sync(0xffffffffu, l, o);
        if (threadIdx.x == 0) g_bsum[blockIdx.x] = l;
    }
    // All g_cnt reads in this block happened before this barrier+fence, so
    // the last block may safely reset g_cnt after the counter saturates.
    __threadfence();
    if (threadIdx.x == 0) slast = (atomicAdd(&g_done, 1) == RBLK - 1);
    __syncthreads();
    if (slast) {
        int t = threadIdx.x;
        float v = g_bsum[t];
        #pragma unroll
        for (int o = 16; o > 0; o >>= 1) v += __shfl_xor_sync(0xffffffffu, v, o);
        __shared__ float s2[8];
        if ((t & 31) == 0) s2[t >> 5] = v;
        __syncthreads();
        if (t < NCLS) g_cnt[t] = 0;   // reset histogram for next replay
        if (t == 0) {
            float s = 0.f;
            #pragma unroll
            for (int i = 0; i < 8; i++) s += s2[i];
            out[0] = s / (float)N_ROWS;
            g_done = 0;               // reset for next replay
        }
    }
}

extern "C" void kernel_launch(void* const* d_in, const int* in_sizes, int n_in,
                              void* d_out, int out_size) {
    const float* x   = (const float*)d_in[0];
    const int*   lab = (const int*)d_in[1];
    if (n_in >= 2 && in_sizes[0] < in_sizes[1]) {
        x   = (const float*)d_in[1];
        lab = (const int*)d_in[0];
    }
    float* out = (float*)d_out;

    // smem: two byte tiles + labels; reuse region scol(33792)+srow(4096) equal.
    size_t smem = (size_t)2 * TI * SROWB + 2 * TI * sizeof(int);
    cudaFuncSetAttribute(k_pair, cudaFuncAttributeMaxDynamicSharedMemorySize, (int)smem);

    k_norm<<<N_ROWS / 8, 256>>>(x, lab);
    k_pair<<<NTILES, 512, smem>>>(lab);
    k_row<<<RBLK, 256>>>(lab, out);
}

// round 15
// speedup vs baseline: 1.7499x; 1.7499x over previous
#include <cuda_runtime.h>
#include <cuda_fp8.h>
#include <cstdint>

#define N_ROWS 8192
#define DIM    128
#define NCLS   64
#define TI     128                 // CTA tile (M = N = 128)
#define NBI    (N_ROWS / TI)       // 64
#define NT     NBI                 // 64 partial slots per row (1 per tile-col)
#define NTILES (NBI * (NBI + 1) / 2)   // 2080 upper-tri tiles
#define SROWB  144                 // padded smem row stride in BYTES (128 data + 16)
#define CPAD   33                  // scol contributor stride (pad vs 32)
#define RBLK   256                 // k_row blocks

// ---- scratch (__device__ globals; no cudaMalloc allowed) ----
__device__ uint8_t g_x8[(size_t)N_ROWS * DIM];     // normalized*sqrt(EXSCALE), e4m3
__device__ float g_negp[(size_t)N_ROWS * NT];      // [row][slot]
__device__ float g_posp[(size_t)N_ROWS * NT];
__device__ int   g_cnt[NCLS];                      // zero at load; k_row resets
__device__ float g_bsum[RBLK];
__device__ int   g_done;                           // zero at load; k_row resets

#define EXSCALE  2.8853900817779268f   // log2(e)/T, T=0.5
#define SQRT_EXS 1.6986436490789138f   // sqrt(EXSCALE)

__device__ __forceinline__ uint32_t smem_u32(const void* p) {
    uint32_t a;
    asm("{ .reg .u64 t; cvta.to.shared.u64 t, %1; cvt.u32.u64 %0, t; }" : "=r"(a) : "l"(p));
    return a;
}
__device__ __forceinline__ float ex2f(float x) {
    float r; asm("ex2.approx.f32 %0, %1;" : "=f"(r) : "f"(x)); return r;
}
__device__ __forceinline__ void ldsm4(uint32_t* r, uint32_t addr) {
    asm volatile("ldmatrix.sync.aligned.m8n8.x4.shared.b16 {%0,%1,%2,%3}, [%4];"
                 : "=r"(r[0]), "=r"(r[1]), "=r"(r[2]), "=r"(r[3]) : "r"(addr));
}
// fp8 e4m3 MMA, fp32 accumulate.
__device__ __forceinline__ void mma16832(float* d, const uint32_t* a,
                                         uint32_t b0, uint32_t b1) {
    asm volatile(
        "mma.sync.aligned.m16n8k32.row.col.f32.e4m3.e4m3.f32 "
        "{%0,%1,%2,%3}, {%4,%5,%6,%7}, {%8,%9}, {%0,%1,%2,%3};"
        : "+f"(d[0]), "+f"(d[1]), "+f"(d[2]), "+f"(d[3])
        : "r"(a[0]), "r"(a[1]), "r"(a[2]), "r"(a[3]), "r"(b0), "r"(b1));
}

// One warp per row: float4 load, shfl reduce, e4m3x4 store. No atomics.
__global__ void k_norm(const float* __restrict__ x) {
    int wid  = (blockIdx.x * 256 + threadIdx.x) >> 5;   // global warp = row
    int lane = threadIdx.x & 31;
    float4 v = *(const float4*)&x[(size_t)wid * DIM + lane * 4];
    float ss = v.x * v.x + v.y * v.y + v.z * v.z + v.w * v.w;
    #pragma unroll
    for (int o = 16; o > 0; o >>= 1) ss += __shfl_xor_sync(0xffffffffu, ss, o);
    float sc = SQRT_EXS / fmaxf(sqrtf(ss), 1e-12f);
    __nv_fp8x2_storage_t lo = __nv_cvt_float2_to_fp8x2(
        make_float2(v.x * sc, v.y * sc), __NV_SATFINITE, __NV_E4M3);
    __nv_fp8x2_storage_t hi = __nv_cvt_float2_to_fp8x2(
        make_float2(v.z * sc, v.w * sc), __NV_SATFINITE, __NV_E4M3);
    uint32_t packed = (uint32_t)lo | ((uint32_t)hi << 16);
    *(uint32_t*)&g_x8[(size_t)wid * DIM + lane * 4] = packed;
}

// Upper-triangular 128x128 Gram tile (bi <= bj), fp8 tensor cores.
// 256 threads, 8 warps in 4(M)x2(N). Row-side partials -> slot bj (halves
// combined via srow smem); column-side -> slot bi (bi<bj) via scol smem.
// Diagonal tiles also accumulate the label histogram (RED, deterministic).
__global__ void __launch_bounds__(256, 2)
k_pair(const int* __restrict__ lab) {
    extern __shared__ char sm[];
    char* As = sm;                                     // [128][SROWB] bytes
    char* Bs = sm + TI * SROWB;                        // [128][SROWB]
    int* labJ = (int*)(Bs + TI * SROWB);               // [128] (survives reuse)
    int* labI = labJ + TI;                             // [128]
    // Post-MMA reuse region (fits under the 36864B tile area):
    float* scol = (float*)sm;                          // [2][128][CPAD] = 33792 B
    float* srow = scol + 2 * 128 * CPAD;               // [2][2][128]    = 2048 B

    int tid  = threadIdx.x;
    int w    = tid >> 5;
    int lane = tid & 31;

    // 1D triangular mapping: t = bj*(bj+1)/2 + bi, bi <= bj.
    int t4 = blockIdx.x;
    int bj = (int)((sqrt(8.0 * (double)t4 + 1.0) - 1.0) * 0.5);
    int bi = t4 - bj * (bj + 1) / 2;
    int i0 = bi * TI;
    int j0 = bj * TI;

    // Cooperative tile load: 16B chunks (8 chunks per 128B row).
    #pragma unroll
    for (int it = 0; it < 8; it++) {
        int idx = tid + it * 256;           // 0..2047
        int sub = idx >> 10;                // 0 = A(i), 1 = B(j)
        int loc = idx & 1023;
        int row = loc >> 3, c = loc & 7;
        int grow = (sub ? j0 : i0) + row;
        uint4 v = *(const uint4*)&g_x8[(size_t)grow * DIM + c * 16];
        char* dst = sub ? Bs : As;
        *(uint4*)(dst + row * SROWB + c * 16) = v;
    }
    if (tid < TI) labJ[tid] = lab[j0 + tid];
    else          labI[tid - TI] = lab[i0 + tid - TI];
    __syncthreads();

    int warp_m = w >> 1;                    // 0..3  -> 32-row slab
    int warp_n = w & 1;                     // 0..1  -> 64-col half
    uint32_t asb = smem_u32(As), bsb = smem_u32(Bs);

    // ldmatrix b16-view of fp8 pairs (byte layout of n8k32 fp8 == n8k16 b16).
    uint32_t a_row = (uint32_t)(warp_m * 32 + (lane & 7) + ((lane >> 3) & 1) * 8);
    uint32_t aaddr = asb + a_row * SROWB + ((lane >> 4) * 16);
    uint32_t b_n = (uint32_t)(warp_n * 64 + ((lane >> 4) << 3) + (lane & 7));
    uint32_t baddr = bsb + b_n * SROWB + (((lane >> 3) & 1) * 16);

    float acc[2][8][4];
    #pragma unroll
    for (int mf = 0; mf < 2; mf++)
        #pragma unroll
        for (int nf = 0; nf < 8; nf++)
            #pragma unroll
            for (int e = 0; e < 4; e++) acc[mf][nf][e] = 0.0f;

    #pragma unroll
    for (int ks = 0; ks < 4; ks++) {       // k32 per step, 4 steps = K128
        uint32_t a[2][4], b[4][4];
        ldsm4(a[0], aaddr + ks * 32);
        ldsm4(a[1], aaddr + 16 * SROWB + ks * 32);
        #pragma unroll
        for (int q = 0; q < 4; q++)
            ldsm4(b[q], baddr + q * 16 * SROWB + ks * 32);
        #pragma unroll
        for (int mf = 0; mf < 2; mf++)
            #pragma unroll
            for (int nf = 0; nf < 8; nf++)
                mma16832(acc[mf][nf], a[mf], b[nf >> 1][(nf & 1) * 2],
                         b[nf >> 1][(nf & 1) * 2 + 1]);
    }

    int lj[8][2];
    #pragma unroll
    for (int nf = 0; nf < 8; nf++) {
        int j = warp_n * 64 + nf * 8 + ((lane & 3) << 1);
        lj[nf][0] = labJ[j];
        lj[nf][1] = labJ[j + 1];
    }
    int li4[2][2];
    #pragma unroll
    for (int mf = 0; mf < 2; mf++)
        #pragma unroll
        for (int rh = 0; rh < 2; rh++)
            li4[mf][rh] = labI[warp_m * 32 + mf * 16 + (lane >> 2) + rh * 8];
    __syncthreads();   // tiles consumed; smem reused as scol/srow (labels intact)

    float colneg[8][2], colpos[8][2];
    #pragma unroll
    for (int nf = 0; nf < 8; nf++)
        colneg[nf][0] = colneg[nf][1] = colpos[nf][0] = colpos[nf][1] = 0.0f;

    // acc = dot*EXSCALE (folded into quantized vectors) -> ex2 directly.
    #pragma unroll
    for (int mf = 0; mf < 2; mf++) {
        #pragma unroll
        for (int rh = 0; rh < 2; rh++) {
            int li = li4[mf][rh];
            float neg = 0.0f, pos = 0.0f;
            #pragma unroll
            for (int nf = 0; nf < 8; nf++) {
                float s0 = ex2f(acc[mf][nf][2 * rh]);
                float s1 = ex2f(acc[mf][nf][2 * rh + 1]);
                neg += s0 + s1;
                colneg[nf][0] += s0;
                colneg[nf][1] += s1;
                if (li == lj[nf][0]) { pos += s0; colpos[nf][0] += s0; }
                if (li == lj[nf][1]) { pos += s1; colpos[nf][1] += s1; }
            }
            neg += __shfl_xor_sync(0xffffffffu, neg, 1);
            neg += __shfl_xor_sync(0xffffffffu, neg, 2);
            pos += __shfl_xor_sync(0xffffffffu, pos, 1);
            pos += __shfl_xor_sync(0xffffffffu, pos, 2);
            if ((lane & 3) == 0) {
                int rloc = warp_m * 32 + mf * 16 + (lane >> 2) + rh * 8;
                srow[warp_n * 128 + rloc]       = neg;   // [half][row] neg
                srow[256 + warp_n * 128 + rloc] = pos;   // [half][row] pos
            }
        }
    }

    // Column-side smem transpose store (32 contributors per column).
    {
        int contrib = warp_m * 8 + (lane >> 2);
        #pragma unroll
        for (int nf = 0; nf < 8; nf++) {
            int col = warp_n * 64 + nf * 8 + ((lane & 3) << 1);
            scol[(col)           * CPAD + contrib] = colneg[nf][0];
            scol[(col + 1)       * CPAD + contrib] = colneg[nf][1];
            scol[(128 + col)     * CPAD + contrib] = colpos[nf][0];
            scol[(128 + col + 1) * CPAD + contrib] = colpos[nf][1];
        }
    }
    __syncthreads();

    // Final phase.
    if (tid < 128) {
        // Row-side: combine the two column halves; single slot bj.
        int r = tid;
        float neg = srow[r] + srow[128 + r];
        float pos = srow[256 + r] + srow[384 + r];
        g_negp[(size_t)(i0 + r) * NT + bj] = neg;
        g_posp[(size_t)(i0 + r) * NT + bj] = pos;
        // Diagonal tiles: label histogram over this tile's 128 rows.
        if (bi == bj && tid < NCLS) {
            int c = 0;
            #pragma unroll 8
            for (int k = 0; k < TI; k++) c += (labJ[k] == tid);
            atomicAdd(&g_cnt[tid], c);
        }
    } else if (bi != bj) {
        // Column-side: sum all 32 contributors; single slot bi.
        int col = tid - 128;
        const float* sn = scol + (col) * CPAD;
        const float* sp = scol + (128 + col) * CPAD;
        float vn = 0.f, vp = 0.f;
        #pragma unroll
        for (int i = 0; i < 32; i++) { vn += sn[i]; vp += sp[i]; }
        g_negp[(size_t)(j0 + col) * NT + bi] = vn;
        g_posp[(size_t)(j0 + col) * NT + bi] = vp;
    }
}

// Per-row loss + fused final reduction. 8 threads/row, 2xfloat4 per array.
// Last block sums partials, writes out, resets g_cnt/g_done for replay.
__global__ void k_row(const int* __restrict__ lab, float* __restrict__ out) {
    int g = blockIdx.x * 256 + threadIdx.x;
    int row = g >> 3, sub = g & 7;
    const float4* np = (const float4*)&g_negp[(size_t)row * NT + sub * 8];
    const float4* pp = (const float4*)&g_posp[(size_t)row * NT + sub * 8];
    float neg = 0.f, pos = 0.f;
    #pragma unroll
    for (int q = 0; q < 2; q++) {
        float4 a = np[q], b = pp[q];
        neg += (a.x + a.y) + (a.z + a.w);
        pos += (b.x + b.y) + (b.z + b.w);
    }
    #pragma unroll
    for (int o = 1; o < 8; o <<= 1) {
        neg += __shfl_xor_sync(0xffffffffu, neg, o);
        pos += __shfl_xor_sync(0xffffffffu, pos, o);
    }
    __shared__ float sl[32];
    __shared__ int slast;
    if (sub == 0) {
        float self = ex2f(EXSCALE);   // exp(1/T): diagonal term
        int cnt = g_cnt[lab[row] & (NCLS - 1)] - 1;
        sl[threadIdx.x >> 3] = logf(neg - self) - logf((pos - self) / (float)cnt);
    }
    __syncthreads();
    if (threadIdx.x < 32) {
        float l = sl[threadIdx.x];
        #pragma unroll
        for (int o = 16; o > 0; o >>= 1) l += __shfl_xor_sync(0xffffffffu, l, o);
        if (threadIdx.x == 0) g_bsum[blockIdx.x] = l;
    }
    // All g_cnt reads in this block precede this fence; last block may reset.
    __threadfence();
    if (threadIdx.x == 0) slast = (atomicAdd(&g_done, 1) == RBLK - 1);
    __syncthreads();
    if (slast) {
        int t = threadIdx.x;
        float v = g_bsum[t];
        #pragma unroll
        for (int o = 16; o > 0; o >>= 1) v += __shfl_xor_sync(0xffffffffu, v, o);
        __shared__ float s2[8];
        if ((t & 31) == 0) s2[t >> 5] = v;
        __syncthreads();
        if (t < NCLS) g_cnt[t] = 0;   // reset histogram for next replay
        if (t == 0) {
            float s = 0.f;
            #pragma unroll
            for (int i = 0; i < 8; i++) s += s2[i];
            out[0] = s / (float)N_ROWS;
            g_done = 0;               // reset for next replay
        }
    }
}

extern "C" void kernel_launch(void* const* d_in, const int* in_sizes, int n_in,
                              void* d_out, int out_size) {
    const float* x   = (const float*)d_in[0];
    const int*   lab = (const int*)d_in[1];
    if (n_in >= 2 && in_sizes[0] < in_sizes[1]) {
        x   = (const float*)d_in[1];
        lab = (const int*)d_in[0];
    }
    float* out = (float*)d_out;

    // smem: two byte tiles (36864) + labels (1024); reuse region is smaller.
    size_t smem = (size_t)2 * TI * SROWB + 2 * TI * sizeof(int);
    cudaFuncSetAttribute(k_pair, cudaFuncAttributeMaxDynamicSharedMemorySize, (int)smem);

    k_norm<<<N_ROWS / 8, 256>>>(x);
    k_pair<<<NTILES, 256, smem>>>(lab);
    k_row<<<RBLK, 256>>>(lab, out);
}

// round 16
// speedup vs baseline: 2.0505x; 1.1718x over previous
#include <cuda_runtime.h>
#include <cuda_fp8.h>
#include <cuda_fp16.h>
#include <cstdint>

#define N_ROWS 8192
#define DIM    128
#define NCLS   64
#define TI     128                 // CTA tile (M = N = 128)
#define NBI    (N_ROWS / TI)       // 64
#define NT     NBI                 // 64 partial slots per row
#define NTILES (NBI * (NBI + 1) / 2)   // 2080 upper-tri tiles
#define SROWB  144                 // padded smem row stride in BYTES
#define CPAD   33                  // scol contributor stride (pad vs 32)
#define RBLK   256                 // k_row blocks

// ---- scratch (__device__ globals; no cudaMalloc allowed) ----
__device__ uint8_t g_x8[(size_t)N_ROWS * DIM];     // normalized*sqrt(EXSCALE), e4m3
__device__ float g_negp[(size_t)N_ROWS * NT];      // [row][slot]
__device__ float g_posp[(size_t)N_ROWS * NT];
__device__ int   g_cnt[NCLS];                      // zero at load; k_row resets
__device__ float g_bsum[RBLK];
__device__ int   g_done;                           // zero at load; k_row resets

#define EXSCALE  2.8853900817779268f   // log2(e)/T, T=0.5
#define SQRT_EXS 1.6986436490789138f   // sqrt(EXSCALE)

__device__ __forceinline__ uint32_t smem_u32(const void* p) {
    uint32_t a;
    asm("{ .reg .u64 t; cvta.to.shared.u64 t, %1; cvt.u32.u64 %0, t; }" : "=r"(a) : "l"(p));
    return a;
}
__device__ __forceinline__ float ex2f(float x) {
    float r; asm("ex2.approx.f32 %0, %1;" : "=f"(r) : "f"(x)); return r;
}
__device__ __forceinline__ uint32_t ex2h2(uint32_t x) {
    uint32_t r; asm("ex2.approx.f16x2 %0, %1;" : "=r"(r) : "r"(x)); return r;
}
__device__ __forceinline__ void ldsm4(uint32_t* r, uint32_t addr) {
    asm volatile("ldmatrix.sync.aligned.m8n8.x4.shared.b16 {%0,%1,%2,%3}, [%4];"
                 : "=r"(r[0]), "=r"(r[1]), "=r"(r[2]), "=r"(r[3]) : "r"(addr));
}
// fp8 e4m3 MMA, f16 accumulate: D = 2 b32 regs, each a (col,col+1) half2.
__device__ __forceinline__ void mma16832h(uint32_t* d, const uint32_t* a,
                                          uint32_t b0, uint32_t b1) {
    asm volatile(
        "mma.sync.aligned.m16n8k32.row.col.f16.e4m3.e4m3.f16 "
        "{%0,%1}, {%2,%3,%4,%5}, {%6,%7}, {%0,%1};"
        : "+r"(d[0]), "+r"(d[1])
        : "r"(a[0]), "r"(a[1]), "r"(a[2]), "r"(a[3]), "r"(b0), "r"(b1));
}
__device__ __forceinline__ __half2 u2h2(uint32_t u) {
    __half2 h; *(uint32_t*)&h = u; return h;
}
__device__ __forceinline__ uint32_t h22u(__half2 h) { return *(uint32_t*)&h; }

// One warp per row: float4 load, shfl reduce, e4m3x4 store. No atomics.
__global__ void k_norm(const float* __restrict__ x) {
    int wid  = (blockIdx.x * 256 + threadIdx.x) >> 5;   // global warp = row
    int lane = threadIdx.x & 31;
    float4 v = *(const float4*)&x[(size_t)wid * DIM + lane * 4];
    float ss = v.x * v.x + v.y * v.y + v.z * v.z + v.w * v.w;
    #pragma unroll
    for (int o = 16; o > 0; o >>= 1) ss += __shfl_xor_sync(0xffffffffu, ss, o);
    float sc = SQRT_EXS / fmaxf(sqrtf(ss), 1e-12f);
    __nv_fp8x2_storage_t lo = __nv_cvt_float2_to_fp8x2(
        make_float2(v.x * sc, v.y * sc), __NV_SATFINITE, __NV_E4M3);
    __nv_fp8x2_storage_t hi = __nv_cvt_float2_to_fp8x2(
        make_float2(v.z * sc, v.w * sc), __NV_SATFINITE, __NV_E4M3);
    uint32_t packed = (uint32_t)lo | ((uint32_t)hi << 16);
    *(uint32_t*)&g_x8[(size_t)wid * DIM + lane * 4] = packed;
}

// Upper-triangular 128x128 Gram tile (bi <= bj), fp8 MMA with f16 accum,
// fully fp16x2-packed epilogue. Row-side partials -> slot bj (halves
// combined via srow smem); column-side -> slot bi via scol smem.
// Diagonal tiles also accumulate the label histogram.
__global__ void __launch_bounds__(256, 2)
k_pair(const int* __restrict__ lab) {
    extern __shared__ char sm[];
    char* As = sm;                                     // [128][SROWB] bytes
    char* Bs = sm + TI * SROWB;                        // [128][SROWB]
    int* labJ = (int*)(Bs + TI * SROWB);               // [128] (survives reuse)
    int* labI = labJ + TI;                             // [128]
    // Post-MMA reuse (under the 36864B tile area):
    uint32_t* scolU = (uint32_t*)sm;                   // [2][64 pairs][CPAD] = 16896 B
    float*    srow  = (float*)(sm + 2 * 64 * CPAD * 4); // [2][2][128] = 2048 B

    int tid  = threadIdx.x;
    int w    = tid >> 5;
    int lane = tid & 31;

    // 1D triangular mapping: t = bj*(bj+1)/2 + bi, bi <= bj.
    int t4 = blockIdx.x;
    int bj = (int)((sqrt(8.0 * (double)t4 + 1.0) - 1.0) * 0.5);
    int bi = t4 - bj * (bj + 1) / 2;
    int i0 = bi * TI;
    int j0 = bj * TI;

    // Cooperative tile load: 16B chunks.
    #pragma unroll
    for (int it = 0; it < 8; it++) {
        int idx = tid + it * 256;           // 0..2047
        int sub = idx >> 10;                // 0 = A(i), 1 = B(j)
        int loc = idx & 1023;
        int row = loc >> 3, c = loc & 7;
        int grow = (sub ? j0 : i0) + row;
        uint4 v = *(const uint4*)&g_x8[(size_t)grow * DIM + c * 16];
        char* dst = sub ? Bs : As;
        *(uint4*)(dst + row * SROWB + c * 16) = v;
    }
    if (tid < TI) labJ[tid] = lab[j0 + tid];
    else          labI[tid - TI] = lab[i0 + tid - TI];
    __syncthreads();

    int warp_m = w >> 1;                    // 0..3  -> 32-row slab
    int warp_n = w & 1;                     // 0..1  -> 64-col half
    uint32_t asb = smem_u32(As), bsb = smem_u32(Bs);

    uint32_t a_row = (uint32_t)(warp_m * 32 + (lane & 7) + ((lane >> 3) & 1) * 8);
    uint32_t aaddr = asb + a_row * SROWB + ((lane >> 4) * 16);
    uint32_t b_n = (uint32_t)(warp_n * 64 + ((lane >> 4) << 3) + (lane & 7));
    uint32_t baddr = bsb + b_n * SROWB + (((lane >> 3) & 1) * 16);

    uint32_t acc2[2][8][2];                 // f16x2 accumulators
    #pragma unroll
    for (int mf = 0; mf < 2; mf++)
        #pragma unroll
        for (int nf = 0; nf < 8; nf++)
            acc2[mf][nf][0] = acc2[mf][nf][1] = 0u;

    #pragma unroll
    for (int ks = 0; ks < 4; ks++) {       // k32 per step, 4 steps = K128
        uint32_t a[2][4], b[4][4];
        ldsm4(a[0], aaddr + ks * 32);
        ldsm4(a[1], aaddr + 16 * SROWB + ks * 32);
        #pragma unroll
        for (int q = 0; q < 4; q++)
            ldsm4(b[q], baddr + q * 16 * SROWB + ks * 32);
        #pragma unroll
        for (int mf = 0; mf < 2; mf++)
            #pragma unroll
            for (int nf = 0; nf < 8; nf++)
                mma16832h(acc2[mf][nf], a[mf], b[nf >> 1][(nf & 1) * 2],
                          b[nf >> 1][(nf & 1) * 2 + 1]);
    }

    // Labels as half2 (values 0..63 exact in f16).
    __half2 lj2[8];
    #pragma unroll
    for (int nf = 0; nf < 8; nf++) {
        int j = warp_n * 64 + nf * 8 + ((lane & 3) << 1);
        lj2[nf] = __halves2half2(__int2half_rn(labJ[j]), __int2half_rn(labJ[j + 1]));
    }
    __half2 li2[2][2];
    #pragma unroll
    for (int mf = 0; mf < 2; mf++)
        #pragma unroll
        for (int rh = 0; rh < 2; rh++) {
            int r = warp_m * 32 + mf * 16 + (lane >> 2) + rh * 8;
            li2[mf][rh] = __half2half2(__int2half_rn(labI[r]));
        }
    __syncthreads();   // tiles consumed; smem reused as scol/srow (labels intact)

    __half2 colneg2[8], colpos2[8];
    #pragma unroll
    for (int nf = 0; nf < 8; nf++) {
        colneg2[nf] = __half2half2(__ushort_as_half(0));
        colpos2[nf] = __half2half2(__ushort_as_half(0));
    }

    // acc = dot*EXSCALE in f16x2 -> packed ex2 + packed masked accumulation.
    #pragma unroll
    for (int mf = 0; mf < 2; mf++) {
        #pragma unroll
        for (int rh = 0; rh < 2; rh++) {
            __half2 li = li2[mf][rh];
            __half2 neg2 = __half2half2(__ushort_as_half(0));
            __half2 pos2 = neg2;
            #pragma unroll
            for (int nf = 0; nf < 8; nf++) {
                __half2 s2 = u2h2(ex2h2(acc2[mf][nf][rh]));
                neg2 = __hadd2(neg2, s2);
                colneg2[nf] = __hadd2(colneg2[nf], s2);
                __half2 m2 = __heq2(li, lj2[nf]);
                pos2 = __hfma2(s2, m2, pos2);
                colpos2[nf] = __hfma2(s2, m2, colpos2[nf]);
            }
            // Reduce across the 4 lanes sharing this row (lane&3 group).
            uint32_t nu = h22u(neg2), pu = h22u(pos2);
            nu = h22u(__hadd2(u2h2(nu), u2h2(__shfl_xor_sync(0xffffffffu, nu, 1))));
            nu = h22u(__hadd2(u2h2(nu), u2h2(__shfl_xor_sync(0xffffffffu, nu, 2))));
            pu = h22u(__hadd2(u2h2(pu), u2h2(__shfl_xor_sync(0xffffffffu, pu, 1))));
            pu = h22u(__hadd2(u2h2(pu), u2h2(__shfl_xor_sync(0xffffffffu, pu, 2))));
            if ((lane & 3) == 0) {
                int rloc = warp_m * 32 + mf * 16 + (lane >> 2) + rh * 8;
                float2 nf2 = __half22float2(u2h2(nu));
                float2 pf2 = __half22float2(u2h2(pu));
                srow[warp_n * 128 + rloc]       = nf2.x + nf2.y;
                srow[256 + warp_n * 128 + rloc] = pf2.x + pf2.y;
            }
        }
    }

    // Column-side packed store: one u32 (half2 = col pair) per nf per array.
    {
        int contrib = warp_m * 8 + (lane >> 2);
        #pragma unroll
        for (int nf = 0; nf < 8; nf++) {
            int cp = warp_n * 32 + nf * 4 + (lane & 3);   // col-pair 0..63
            scolU[(cp)      * CPAD + contrib] = h22u(colneg2[nf]);
            scolU[(64 + cp) * CPAD + contrib] = h22u(colpos2[nf]);
        }
    }
    __syncthreads();

    // Final phase.
    if (tid < 128) {
        // Row-side: combine the two column halves; single slot bj.
        int r = tid;
        float neg = srow[r] + srow[128 + r];
        float pos = srow[256 + r] + srow[384 + r];
        g_negp[(size_t)(i0 + r) * NT + bj] = neg;
        g_posp[(size_t)(i0 + r) * NT + bj] = pos;
        // Diagonal tiles: label histogram over this tile's 128 rows.
        if (bi == bj && tid < NCLS) {
            int c = 0;
            #pragma unroll 8
            for (int k = 0; k < TI; k++) c += (labJ[k] == tid);
            atomicAdd(&g_cnt[tid], c);
        }
    } else if (bi != bj) {
        // Column-side: 128 items = 2 arrays x 64 col-pairs; sum 32 contributors.
        int idx = tid - 128;
        int arr = idx >> 6, cp = idx & 63;
        const uint32_t* s = scolU + (arr * 64 + cp) * CPAD;
        float v0 = 0.f, v1 = 0.f;
        #pragma unroll
        for (int i = 0; i < 32; i++) {
            float2 f = __half22float2(u2h2(s[i]));
            v0 += f.x; v1 += f.y;
        }
        float* g = arr ? g_posp : g_negp;
        g[(size_t)(j0 + 2 * cp)     * NT + bi] = v0;
        g[(size_t)(j0 + 2 * cp + 1) * NT + bi] = v1;
    }
}

// Per-row loss + fused final reduction. 8 threads/row, 2xfloat4 per array.
__global__ void k_row(const int* __restrict__ lab, float* __restrict__ out) {
    int g = blockIdx.x * 256 + threadIdx.x;
    int row = g >> 3, sub = g & 7;
    const float4* np = (const float4*)&g_negp[(size_t)row * NT + sub * 8];
    const float4* pp = (const float4*)&g_posp[(size_t)row * NT + sub * 8];
    float neg = 0.f, pos = 0.f;
    #pragma unroll
    for (int q = 0; q < 2; q++) {
        float4 a = np[q], b = pp[q];
        neg += (a.x + a.y) + (a.z + a.w);
        pos += (b.x + b.y) + (b.z + b.w);
    }
    #pragma unroll
    for (int o = 1; o < 8; o <<= 1) {
        neg += __shfl_xor_sync(0xffffffffu, neg, o);
        pos += __shfl_xor_sync(0xffffffffu, pos, o);
    }
    __shared__ float sl[32];
    __shared__ int slast;
    if (sub == 0) {
        float self = ex2f(EXSCALE);   // exp(1/T): diagonal term
        int cnt = g_cnt[lab[row] & (NCLS - 1)] - 1;
        sl[threadIdx.x >> 3] = logf(neg - self) - logf((pos - self) / (float)cnt);
    }
    __syncthreads();
    if (threadIdx.x < 32) {
        float l = sl[threadIdx.x];
        #pragma unroll
        for (int o = 16; o > 0; o >>= 1) l += __shfl_xor_sync(0xffffffffu, l, o);
        if (threadIdx.x == 0) g_bsum[blockIdx.x] = l;
    }
    __threadfence();
    if (threadIdx.x == 0) slast = (atomicAdd(&g_done, 1) == RBLK - 1);
    __syncthreads();
    if (slast) {
        int t = threadIdx.x;
        float v = g_bsum[t];
        #pragma unroll
        for (int o = 16; o > 0; o >>= 1) v += __shfl_xor_sync(0xffffffffu, v, o);
        __shared__ float s2[8];
        if ((t & 31) == 0) s2[t >> 5] = v;
        __syncthreads();
        if (t < NCLS) g_cnt[t] = 0;   // reset histogram for next replay
        if (t == 0) {
            float s = 0.f;
            #pragma unroll
            for (int i = 0; i < 8; i++) s += s2[i];
            out[0] = s / (float)N_ROWS;
            g_done = 0;               // reset for next replay
        }
    }
}

extern "C" void kernel_launch(void* const* d_in, const int* in_sizes, int n_in,
                              void* d_out, int out_size) {
    const float* x   = (const float*)d_in[0];
    const int*   lab = (const int*)d_in[1];
    if (n_in >= 2 && in_sizes[0] < in_sizes[1]) {
        x   = (const float*)d_in[1];
        lab = (const int*)d_in[0];
    }
    float* out = (float*)d_out;

    size_t smem = (size_t)2 * TI * SROWB + 2 * TI * sizeof(int);
    cudaFuncSetAttribute(k_pair, cudaFuncAttributeMaxDynamicSharedMemorySize, (int)smem);

    k_norm<<<N_ROWS / 8, 256>>>(x);
    k_pair<<<NTILES, 256, smem>>>(lab);
    k_row<<<RBLK, 256>>>(lab, out);
}

// round 17
// speedup vs baseline: 2.1694x; 1.0580x over previous
#include <cuda_runtime.h>
#include <cuda_fp8.h>
#include <cuda_fp16.h>
#include <cstdint>

#define N_ROWS 8192
#define DIM    128
#define NCLS   64
#define TI     128                 // CTA tile (M = N = 128)
#define NBI    (N_ROWS / TI)       // 64
#define NT     NBI                 // 64 partial slots per row
#define NTILES (NBI * (NBI + 1) / 2)   // 2080 upper-tri tiles
#define SROWB  144                 // padded smem row stride in BYTES
#define CPAD   33                  // scol contributor stride (pad vs 32)
#define RBLK   256                 // k_row blocks

// ---- scratch (__device__ globals; no cudaMalloc allowed) ----
__device__ uint8_t g_x8[(size_t)N_ROWS * DIM];     // normalized*sqrt(EXSCALE), e4m3
__device__ float g_negp[(size_t)N_ROWS * NT];      // [row][slot]
__device__ float g_posp[(size_t)N_ROWS * NT];
__device__ int   g_cnt[NCLS];                      // zero at load; k_row resets
__device__ float g_bsum[RBLK];
__device__ int   g_done;                           // zero at load; k_row resets

#define EXSCALE  2.8853900817779268f   // log2(e)/T, T=0.5
#define SQRT_EXS 1.6986436490789138f   // sqrt(EXSCALE)

__device__ __forceinline__ uint32_t smem_u32(const void* p) {
    uint32_t a;
    asm("{ .reg .u64 t; cvta.to.shared.u64 t, %1; cvt.u32.u64 %0, t; }" : "=r"(a) : "l"(p));
    return a;
}
__device__ __forceinline__ float ex2f(float x) {
    float r; asm("ex2.approx.f32 %0, %1;" : "=f"(r) : "f"(x)); return r;
}
__device__ __forceinline__ uint32_t ex2h2(uint32_t x) {
    uint32_t r; asm("ex2.approx.f16x2 %0, %1;" : "=r"(r) : "r"(x)); return r;
}
__device__ __forceinline__ void ldsm4(uint32_t* r, uint32_t addr) {
    asm volatile("ldmatrix.sync.aligned.m8n8.x4.shared.b16 {%0,%1,%2,%3}, [%4];"
                 : "=r"(r[0]), "=r"(r[1]), "=r"(r[2]), "=r"(r[3]) : "r"(addr));
}
// fp8 e4m3 MMA, f16 accumulate: D = 2 b32 regs, each a (col,col+1) half2.
__device__ __forceinline__ void mma16832h(uint32_t* d, const uint32_t* a,
                                          uint32_t b0, uint32_t b1) {
    asm volatile(
        "mma.sync.aligned.m16n8k32.row.col.f16.e4m3.e4m3.f16 "
        "{%0,%1}, {%2,%3,%4,%5}, {%6,%7}, {%0,%1};"
        : "+r"(d[0]), "+r"(d[1])
        : "r"(a[0]), "r"(a[1]), "r"(a[2]), "r"(a[3]), "r"(b0), "r"(b1));
}
__device__ __forceinline__ __half2 u2h2(uint32_t u) {
    __half2 h; *(uint32_t*)&h = u; return h;
}
__device__ __forceinline__ uint32_t h22u(__half2 h) { return *(uint32_t*)&h; }

// Two rows per warp (MLP=2): float4 loads, interleaved shfl reduces, no atomics.
__global__ void k_norm(const float* __restrict__ x) {
    int wid  = (blockIdx.x * 256 + threadIdx.x) >> 5;   // global warp
    int lane = threadIdx.x & 31;
    int r0 = wid * 2, r1 = r0 + 1;
    float4 v0 = *(const float4*)&x[(size_t)r0 * DIM + lane * 4];
    float4 v1 = *(const float4*)&x[(size_t)r1 * DIM + lane * 4];
    float s0 = v0.x * v0.x + v0.y * v0.y + v0.z * v0.z + v0.w * v0.w;
    float s1 = v1.x * v1.x + v1.y * v1.y + v1.z * v1.z + v1.w * v1.w;
    #pragma unroll
    for (int o = 16; o > 0; o >>= 1) {
        s0 += __shfl_xor_sync(0xffffffffu, s0, o);
        s1 += __shfl_xor_sync(0xffffffffu, s1, o);
    }
    float c0 = SQRT_EXS / fmaxf(sqrtf(s0), 1e-12f);
    float c1 = SQRT_EXS / fmaxf(sqrtf(s1), 1e-12f);
    __nv_fp8x2_storage_t a0 = __nv_cvt_float2_to_fp8x2(
        make_float2(v0.x * c0, v0.y * c0), __NV_SATFINITE, __NV_E4M3);
    __nv_fp8x2_storage_t a1 = __nv_cvt_float2_to_fp8x2(
        make_float2(v0.z * c0, v0.w * c0), __NV_SATFINITE, __NV_E4M3);
    __nv_fp8x2_storage_t b0 = __nv_cvt_float2_to_fp8x2(
        make_float2(v1.x * c1, v1.y * c1), __NV_SATFINITE, __NV_E4M3);
    __nv_fp8x2_storage_t b1 = __nv_cvt_float2_to_fp8x2(
        make_float2(v1.z * c1, v1.w * c1), __NV_SATFINITE, __NV_E4M3);
    *(uint32_t*)&g_x8[(size_t)r0 * DIM + lane * 4] = (uint32_t)a0 | ((uint32_t)a1 << 16);
    *(uint32_t*)&g_x8[(size_t)r1 * DIM + lane * 4] = (uint32_t)b0 | ((uint32_t)b1 << 16);
}

// Upper-triangular 128x128 Gram tile (bi <= bj), fp8 MMA with f16 accum,
// fp16x2-packed epilogue, 3 CTAs/SM. Row-side partials -> slot bj; column-
// side -> slot bi via scol smem. Diagonal tiles build the label histogram.
__global__ void __launch_bounds__(256, 3)
k_pair(const int* __restrict__ lab) {
    extern __shared__ char sm[];
    char* As = sm;                                     // [128][SROWB] bytes
    char* Bs = sm + TI * SROWB;                        // [128][SROWB]
    int* labJ = (int*)(Bs + TI * SROWB);               // [128] (survives reuse)
    int* labI = labJ + TI;                             // [128]
    // Post-MMA reuse (under the 36864B tile area):
    uint32_t* scolU = (uint32_t*)sm;                   // [2][64 pairs][CPAD] = 16896 B
    float*    srow  = (float*)(sm + 2 * 64 * CPAD * 4); // [2][2][128] = 2048 B

    int tid  = threadIdx.x;
    int w    = tid >> 5;
    int lane = tid & 31;

    // 1D triangular mapping: t = bj*(bj+1)/2 + bi, bi <= bj.
    int t4 = blockIdx.x;
    int bj = (int)((sqrt(8.0 * (double)t4 + 1.0) - 1.0) * 0.5);
    int bi = t4 - bj * (bj + 1) / 2;
    int i0 = bi * TI;
    int j0 = bj * TI;

    // Cooperative tile load: 16B chunks.
    #pragma unroll
    for (int it = 0; it < 8; it++) {
        int idx = tid + it * 256;           // 0..2047
        int sub = idx >> 10;                // 0 = A(i), 1 = B(j)
        int loc = idx & 1023;
        int row = loc >> 3, c = loc & 7;
        int grow = (sub ? j0 : i0) + row;
        uint4 v = *(const uint4*)&g_x8[(size_t)grow * DIM + c * 16];
        char* dst = sub ? Bs : As;
        *(uint4*)(dst + row * SROWB + c * 16) = v;
    }
    if (tid < TI) labJ[tid] = lab[j0 + tid];
    else          labI[tid - TI] = lab[i0 + tid - TI];
    __syncthreads();

    int warp_m = w >> 1;                    // 0..3  -> 32-row slab
    int warp_n = w & 1;                     // 0..1  -> 64-col half
    uint32_t asb = smem_u32(As), bsb = smem_u32(Bs);

    uint32_t a_row = (uint32_t)(warp_m * 32 + (lane & 7) + ((lane >> 3) & 1) * 8);
    uint32_t aaddr = asb + a_row * SROWB + ((lane >> 4) * 16);
    uint32_t b_n = (uint32_t)(warp_n * 64 + ((lane >> 4) << 3) + (lane & 7));
    uint32_t baddr = bsb + b_n * SROWB + (((lane >> 3) & 1) * 16);

    uint32_t acc2[2][8][2];                 // f16x2 accumulators
    #pragma unroll
    for (int mf = 0; mf < 2; mf++)
        #pragma unroll
        for (int nf = 0; nf < 8; nf++)
            acc2[mf][nf][0] = acc2[mf][nf][1] = 0u;

    #pragma unroll
    for (int ks = 0; ks < 4; ks++) {       // k32 per step, 4 steps = K128
        uint32_t a[2][4], b[4][4];
        ldsm4(a[0], aaddr + ks * 32);
        ldsm4(a[1], aaddr + 16 * SROWB + ks * 32);
        #pragma unroll
        for (int q = 0; q < 4; q++)
            ldsm4(b[q], baddr + q * 16 * SROWB + ks * 32);
        #pragma unroll
        for (int mf = 0; mf < 2; mf++)
            #pragma unroll
            for (int nf = 0; nf < 8; nf++)
                mma16832h(acc2[mf][nf], a[mf], b[nf >> 1][(nf & 1) * 2],
                          b[nf >> 1][(nf & 1) * 2 + 1]);
    }

    // Labels as half2 (values 0..63 exact in f16).
    __half2 lj2[8];
    #pragma unroll
    for (int nf = 0; nf < 8; nf++) {
        int j = warp_n * 64 + nf * 8 + ((lane & 3) << 1);
        lj2[nf] = __halves2half2(__int2half_rn(labJ[j]), __int2half_rn(labJ[j + 1]));
    }
    __half2 li2[2][2];
    #pragma unroll
    for (int mf = 0; mf < 2; mf++)
        #pragma unroll
        for (int rh = 0; rh < 2; rh++) {
            int r = warp_m * 32 + mf * 16 + (lane >> 2) + rh * 8;
            li2[mf][rh] = __half2half2(__int2half_rn(labI[r]));
        }
    __syncthreads();   // tiles consumed; smem reused as scol/srow (labels intact)

    __half2 colneg2[8], colpos2[8];
    #pragma unroll
    for (int nf = 0; nf < 8; nf++) {
        colneg2[nf] = __half2half2(__ushort_as_half(0));
        colpos2[nf] = __half2half2(__ushort_as_half(0));
    }

    // acc = dot*EXSCALE in f16x2 -> packed ex2 + packed masked accumulation.
    #pragma unroll
    for (int mf = 0; mf < 2; mf++) {
        #pragma unroll
        for (int rh = 0; rh < 2; rh++) {
            __half2 li = li2[mf][rh];
            __half2 neg2 = __half2half2(__ushort_as_half(0));
            __half2 pos2 = neg2;
            #pragma unroll
            for (int nf = 0; nf < 8; nf++) {
                __half2 s2 = u2h2(ex2h2(acc2[mf][nf][rh]));
                neg2 = __hadd2(neg2, s2);
                colneg2[nf] = __hadd2(colneg2[nf], s2);
                __half2 m2 = __heq2(li, lj2[nf]);
                pos2 = __hfma2(s2, m2, pos2);
                colpos2[nf] = __hfma2(s2, m2, colpos2[nf]);
            }
            // Reduce across the 4 lanes sharing this row (lane&3 group).
            uint32_t nu = h22u(neg2), pu = h22u(pos2);
            nu = h22u(__hadd2(u2h2(nu), u2h2(__shfl_xor_sync(0xffffffffu, nu, 1))));
            nu = h22u(__hadd2(u2h2(nu), u2h2(__shfl_xor_sync(0xffffffffu, nu, 2))));
            pu = h22u(__hadd2(u2h2(pu), u2h2(__shfl_xor_sync(0xffffffffu, pu, 1))));
            pu = h22u(__hadd2(u2h2(pu), u2h2(__shfl_xor_sync(0xffffffffu, pu, 2))));
            if ((lane & 3) == 0) {
                int rloc = warp_m * 32 + mf * 16 + (lane >> 2) + rh * 8;
                float2 nf2 = __half22float2(u2h2(nu));
                float2 pf2 = __half22float2(u2h2(pu));
                srow[warp_n * 128 + rloc]       = nf2.x + nf2.y;
                srow[256 + warp_n * 128 + rloc] = pf2.x + pf2.y;
            }
        }
    }

    // Column-side packed store: one u32 (half2 = col pair) per nf per array.
    {
        int contrib = warp_m * 8 + (lane >> 2);
        #pragma unroll
        for (int nf = 0; nf < 8; nf++) {
            int cp = warp_n * 32 + nf * 4 + (lane & 3);   // col-pair 0..63
            scolU[(cp)      * CPAD + contrib] = h22u(colneg2[nf]);
            scolU[(64 + cp) * CPAD + contrib] = h22u(colpos2[nf]);
        }
    }
    __syncthreads();

    // Final phase.
    if (tid < 128) {
        // Row-side: combine the two column halves; single slot bj.
        int r = tid;
        float neg = srow[r] + srow[128 + r];
        float pos = srow[256 + r] + srow[384 + r];
        g_negp[(size_t)(i0 + r) * NT + bj] = neg;
        g_posp[(size_t)(i0 + r) * NT + bj] = pos;
        // Diagonal tiles: label histogram over this tile's 128 rows.
        if (bi == bj && tid < NCLS) {
            int c = 0;
            #pragma unroll 8
            for (int k = 0; k < TI; k++) c += (labJ[k] == tid);
            atomicAdd(&g_cnt[tid], c);
        }
    } else if (bi != bj) {
        // Column-side: 128 items = 2 arrays x 64 col-pairs; sum 32 contributors.
        int idx = tid - 128;
        int arr = idx >> 6, cp = idx & 63;
        const uint32_t* s = scolU + (arr * 64 + cp) * CPAD;
        float v0 = 0.f, v1 = 0.f;
        #pragma unroll
        for (int i = 0; i < 32; i++) {
            float2 f = __half22float2(u2h2(s[i]));
            v0 += f.x; v1 += f.y;
        }
        float* g = arr ? g_posp : g_negp;
        g[(size_t)(j0 + 2 * cp)     * NT + bi] = v0;
        g[(size_t)(j0 + 2 * cp + 1) * NT + bi] = v1;
    }
}

// Per-row loss + fused final reduction. 8 threads/row, 2xfloat4 per array.
__global__ void k_row(const int* __restrict__ lab, float* __restrict__ out) {
    int g = blockIdx.x * 256 + threadIdx.x;
    int row = g >> 3, sub = g & 7;
    const float4* np = (const float4*)&g_negp[(size_t)row * NT + sub * 8];
    const float4* pp = (const float4*)&g_posp[(size_t)row * NT + sub * 8];
    float neg = 0.f, pos = 0.f;
    #pragma unroll
    for (int q = 0; q < 2; q++) {
        float4 a = np[q], b = pp[q];
        neg += (a.x + a.y) + (a.z + a.w);
        pos += (b.x + b.y) + (b.z + b.w);
    }
    #pragma unroll
    for (int o = 1; o < 8; o <<= 1) {
        neg += __shfl_xor_sync(0xffffffffu, neg, o);
        pos += __shfl_xor_sync(0xffffffffu, pos, o);
    }
    __shared__ float sl[32];
    __shared__ int slast;
    if (sub == 0) {
        float self = ex2f(EXSCALE);   // exp(1/T): diagonal term
        int cnt = g_cnt[lab[row] & (NCLS - 1)] - 1;
        sl[threadIdx.x >> 3] = logf(neg - self) - logf((pos - self) / (float)cnt);
    }
    __syncthreads();
    if (threadIdx.x < 32) {
        float l = sl[threadIdx.x];
        #pragma unroll
        for (int o = 16; o > 0; o >>= 1) l += __shfl_xor_sync(0xffffffffu, l, o);
        if (threadIdx.x == 0) g_bsum[blockIdx.x] = l;
    }
    __threadfence();
    if (threadIdx.x == 0) slast = (atomicAdd(&g_done, 1) == RBLK - 1);
    __syncthreads();
    if (slast) {
        int t = threadIdx.x;
        float v = g_bsum[t];
        #pragma unroll
        for (int o = 16; o > 0; o >>= 1) v += __shfl_xor_sync(0xffffffffu, v, o);
        __shared__ float s2[8];
        if ((t & 31) == 0) s2[t >> 5] = v;
        __syncthreads();
        if (t < NCLS) g_cnt[t] = 0;   // reset histogram for next replay
        if (t == 0) {
            float s = 0.f;
            #pragma unroll
            for (int i = 0; i < 8; i++) s += s2[i];
            out[0] = s / (float)N_ROWS;
            g_done = 0;               // reset for next replay
        }
    }
}

extern "C" void kernel_launch(void* const* d_in, const int* in_sizes, int n_in,
                              void* d_out, int out_size) {
    const float* x   = (const float*)d_in[0];
    const int*   lab = (const int*)d_in[1];
    if (n_in >= 2 && in_sizes[0] < in_sizes[1]) {
        x   = (const float*)d_in[1];
        lab = (const int*)d_in[0];
    }
    float* out = (float*)d_out;

    size_t smem = (size_t)2 * TI * SROWB + 2 * TI * sizeof(int);
    cudaFuncSetAttribute(k_pair, cudaFuncAttributeMaxDynamicSharedMemorySize, (int)smem);

    k_norm<<<N_ROWS / 16, 256>>>(x);
    k_pair<<<NTILES, 256, smem>>>(lab);
    k_row<<<RBLK, 256>>>(lab, out);
}